// round 11
// baseline (speedup 1.0000x reference)
#include <cuda_runtime.h>

#define E_EDGES 250000
#define TILE_E  64
#define NBLOCKS ((E_EDGES + TILE_E - 1) / TILE_E)
#define GRID    444   /* 3 CTAs x 148 SMs, persistent */

using u64 = unsigned long long;

__device__ float g_wsh[12288];   // pre-swizzled W image (exact smem layout)

__device__ __forceinline__ u64 ffma2(u64 a, u64 b, u64 c) {
    u64 d;
    asm("fma.rn.f32x2 %0, %1, %2, %3;" : "=l"(d) : "l"(a), "l"(b), "l"(c));
    return d;
}
__device__ __forceinline__ u64 dup2(float x) {
    u64 d;
    asm("mov.b64 %0, {%1, %1};" : "=l"(d) : "f"(x));
    return d;
}
__device__ __forceinline__ float lo32(u64 v) { return __uint_as_float((unsigned)(v & 0xffffffffu)); }
__device__ __forceinline__ float hi32(u64 v) { return __uint_as_float((unsigned)(v >> 32)); }

// W layout per (d,q): base = d*192 + q*48 floats   (q = channel quarter, c0 = q*16+2cp)
//   blockA [0,32):  cp*4 -> {W[c0][r0], W[c1][r0], W[c0][r1], W[c1][r1]}
//   blockB [32,48): cp*2 -> {W[c0][r2], W[c1][r2]}
__global__ void prep_w_kernel(const float* __restrict__ W) {
    int o = blockIdx.x * 256 + threadIdx.x;
    if (o < 12288) {
        int d    = o / 192;
        int rem  = o - d * 192;
        int q    = rem / 48;
        int rem2 = rem - q * 48;
        int c, r;
        if (rem2 < 32) {
            int cp = rem2 >> 2, t = rem2 & 3;
            c = q * 16 + 2 * cp + (t & 1);
            r = t >> 1;
        } else {
            int rem3 = rem2 - 32;
            int cp = rem3 >> 1;
            c = q * 16 + 2 * cp + (rem3 & 1);
            r = 2;
        }
        g_wsh[o] = W[d * 192 + c * 3 + r];
    }
}

// Shared layout (bytes):
//   wsh  : float[12288]  [0, 49152)     persistent
//   overlay [49152, 68608):  invs rows stride 68 (17408B) / epilogue stage
//            (8 warps x 608 words; rows at {0,144,288,432}, 576 words used)
//   shs  : float[64*12]  [68608, 71680)
#define SMEM_BYTES 71680

// fill index remap: warp covers 4 edges x 8 consecutive d -> conflict-free STS
__device__ __forceinline__ void fill_map(int idx, int& el, int& d) {
    el = (idx & 3) | ((idx >> 3) & 0x3C);
    d  = ((idx >> 2) & 7) | ((idx >> 6) & 0x38);
}

__device__ __forceinline__ void sh_from_vec(float x, float y, float z, float* o) {
    float r = rsqrtf(x * x + y * y + z * z);
    x *= r; y *= r; z *= r;
    const float s3  = 1.7320508075688772f;
    const float s5  = 2.2360679774997896f;
    const float s15 = 3.8729833462074170f;
    o[0] = 1.0f;
    o[1] = s3 * x;
    o[2] = s3 * y;
    o[3] = s3 * z;
    o[4] = s15 * x * z;
    o[5] = s15 * x * y;
    o[6] = s5 * (y * y - 0.5f * (x * x + z * z));
    o[7] = s15 * y * z;
    o[8] = 0.5f * s15 * (z * z - x * x);
}

__global__ __launch_bounds__(256, 3)
void sh_tensor_embed_kernel(const float* __restrict__ vec,
                            const float* __restrict__ inv,
                            float* __restrict__ out) {
    extern __shared__ char sm[];
    float* smf  = (float*)sm;
    float* invs = (float*)(sm + 49152);
    float* shs  = (float*)(sm + 68608);

    const int tid  = threadIdx.x;
    const int lane = tid & 31;
    const int wid  = tid >> 5;
    const int cp   = lane & 7;           // channel pair within quarter
    const int oct  = lane >> 3;          // edge octet within half (0..3)
    const int q    = wid & 3;            // channel quarter: channels [16q, 16q+16)
    const int eh2  = wid >> 2;           // edge half: edges [32*eh2, 32*eh2+32)

    // stage row base per oct: {0,144,288,432} words — 16B-aligned; bases mod 32
    // = {0,16,0,16} so STS.64 lanes cover all even banks exactly 2x (byte floor)
    const int Boct = oct * 144;

    // ---- one-time W fill ----
    #pragma unroll
    for (int it = 0; it < 12; it++) {
        int idx = it * 256 + tid;
        ((float4*)smf)[idx] = ((const float4*)g_wsh)[idx];
    }
    // ---- fill first tile's invs + shs ----
    {
        int e0 = blockIdx.x * TILE_E;
        #pragma unroll
        for (int k = 0; k < 16; k++) {
            int el, d;
            fill_map(tid + 256 * k, el, d);
            int e = e0 + el; if (e >= E_EDGES) e = E_EDGES - 1;
            invs[d * 68 + el] = inv[(size_t)e * 64 + d];   // conflict-free STS
        }
        if (tid < TILE_E) {
            int e = e0 + tid; if (e >= E_EDGES) e = E_EDGES - 1;
            sh_from_vec(vec[(size_t)e * 3], vec[(size_t)e * 3 + 1], vec[(size_t)e * 3 + 2],
                        shs + tid * 12);
        }
    }
    __syncthreads();

    const char* wpA = (const char*)(smf + q * 48 + cp * 4);        // LDS.128 / d
    const char* wpB = (const char*)(smf + q * 48 + 32 + cp * 2);   // LDS.64  / d
    float* stagew = invs + wid * 608;    // overlay (invs dead during epilogue)

    for (int tile = blockIdx.x; tile < NBLOCKS; tile += GRID) {
        const int e0 = tile * TILE_E;

        // ---- mainloop: 2 channels (q*16+2cp,+1) x 8 edges (octet oct of half eh2) ----
        u64 acc[8][3];
        #pragma unroll
        for (int j = 0; j < 8; j++)
            #pragma unroll
            for (int r = 0; r < 3; r++)
                acc[j][r] = 0ull;

        const float* ip = invs + eh2 * 32 + oct * 8;

        #pragma unroll 2
        for (int d = 0; d < 64; d++) {
            ulonglong2 wab = *(const ulonglong2*)(wpA + d * 768);  // {wv0, wv1}
            u64 wv2        = *(const u64*)      (wpB + d * 768);
            float iv[8];
            *(float4*)&iv[0] = *(const float4*)(ip + d * 68);      // 4-addr LDS.128
            *(float4*)&iv[4] = *(const float4*)(ip + d * 68 + 4);
            #pragma unroll
            for (int j = 0; j < 8; j++) {
                u64 pv = dup2(iv[j]);
                acc[j][0] = ffma2(pv, wab.x, acc[j][0]);
                acc[j][1] = ffma2(pv, wab.y, acc[j][1]);
                acc[j][2] = ffma2(pv, wv2,   acc[j][2]);
            }
        }
        __syncthreads();                 // invs reads done -> stage overlay safe

        // ---- prefetch next tile while epilogue runs ----
        const int nt = tile + GRID;
        const bool nxt = nt < NBLOCKS;
        float pv[16];
        float vx = 0.f, vy = 0.f, vz = 0.f;
        if (nxt) {
            int ne0 = nt * TILE_E;
            #pragma unroll
            for (int k = 0; k < 16; k++) {
                int el, d;
                fill_map(tid + 256 * k, el, d);
                int e = ne0 + el; if (e >= E_EDGES) e = E_EDGES - 1;
                pv[k] = inv[(size_t)e * 64 + d];
            }
            if (tid < TILE_E) {
                int e = ne0 + tid; if (e >= E_EDGES) e = E_EDGES - 1;
                vx = vec[(size_t)e * 3];
                vy = vec[(size_t)e * 3 + 1];
                vz = vec[(size_t)e * 3 + 2];
            }
        }

        // ---- epilogue: 8 rounds; each round stages 4 edges (one per oct) ----
        #pragma unroll
        for (int s = 0; s < 8; s++) {
            {
                int el = eh2 * 32 + oct * 8 + s;
                const float* sb = shs + el * 12;
                float4 sa  = *(const float4*)sb;
                float4 sbv = *(const float4*)(sb + 4);
                float  s8  = sb[8];
                float sv[9] = {sa.x, sa.y, sa.z, sa.w, sbv.x, sbv.y, sbv.z, sbv.w, s8};
                float wa[3], wb[3];
                #pragma unroll
                for (int r = 0; r < 3; r++) { wa[r] = lo32(acc[s][r]); wb[r] = hi32(acc[s][r]); }
                float v[18];
                #pragma unroll
                for (int k = 0; k < 9; k++) {
                    int r = (k == 0) ? 0 : ((k < 4) ? 1 : 2);
                    v[k]     = sv[k] * wa[r];
                    v[9 + k] = sv[k] * wb[r];
                }
                float* rowp = stagew + Boct + cp * 18;
                #pragma unroll
                for (int p = 0; p < 9; p++)
                    *(float2*)(rowp + 2 * p) = make_float2(v[2 * p], v[2 * p + 1]);
            }
            __syncwarp();
            #pragma unroll
            for (int t = 0; t < 4; t++) {
                int e = e0 + eh2 * 32 + t * 8 + s;
                if (e < E_EDGES) {
                    const float4* src = (const float4*)(stagew + t * 144);
                    float4* dst = (float4*)(out + (size_t)e * 576 + q * 144);
                    dst[lane] = src[lane];                    // 32 of 36 float4
                    if (lane < 4) dst[32 + lane] = src[32 + lane];
                }
            }
            __syncwarp();
        }
        __syncthreads();                 // stage reads done -> invs refill safe

        // ---- commit prefetched tile (conflict-free STS) ----
        if (nxt) {
            #pragma unroll
            for (int k = 0; k < 16; k++) {
                int el, d;
                fill_map(tid + 256 * k, el, d);
                invs[d * 68 + el] = pv[k];
            }
            if (tid < TILE_E)
                sh_from_vec(vx, vy, vz, shs + tid * 12);
        }
        __syncthreads();
    }
}

extern "C" void kernel_launch(void* const* d_in, const int* in_sizes, int n_in,
                              void* d_out, int out_size) {
    const float* vec = nullptr;
    const float* inv = nullptr;
    const float* W   = nullptr;
    for (int i = 0; i < n_in; i++) {
        if      (in_sizes[i] == E_EDGES * 3)  vec = (const float*)d_in[i];
        else if (in_sizes[i] == E_EDGES * 64) inv = (const float*)d_in[i];
        else if (in_sizes[i] == 64 * 192)     W   = (const float*)d_in[i];
    }
    prep_w_kernel<<<48, 256>>>(W);
    cudaFuncSetAttribute(sh_tensor_embed_kernel,
                         cudaFuncAttributeMaxDynamicSharedMemorySize, SMEM_BYTES);
    sh_tensor_embed_kernel<<<GRID, 256, SMEM_BYTES>>>(vec, inv, (float*)d_out);
}

// round 13
// speedup vs baseline: 1.0270x; 1.0270x over previous
#include <cuda_runtime.h>

#define E_EDGES 250000
#define TILE_E  64
#define NBLOCKS ((E_EDGES + TILE_E - 1) / TILE_E)
#define GRID    444   /* 3 CTAs x 148 SMs, persistent */

using u64 = unsigned long long;

__device__ float g_wsh[12288];   // pre-swizzled W image (exact smem layout)

__device__ __forceinline__ u64 ffma2(u64 a, u64 b, u64 c) {
    u64 d;
    asm("fma.rn.f32x2 %0, %1, %2, %3;" : "=l"(d) : "l"(a), "l"(b), "l"(c));
    return d;
}
__device__ __forceinline__ u64 dup2(float x) {
    u64 d;
    asm("mov.b64 %0, {%1, %1};" : "=l"(d) : "f"(x));
    return d;
}
__device__ __forceinline__ float lo32(u64 v) { return __uint_as_float((unsigned)(v & 0xffffffffu)); }
__device__ __forceinline__ float hi32(u64 v) { return __uint_as_float((unsigned)(v >> 32)); }

// W layout per (d,h): base = d*192 + h*96 floats   (h = channel half, c0 = h*32+2cp)
//   blockA [0,64):  cp*4 -> {W[c0][r0], W[c1][r0], W[c0][r1], W[c1][r1]}
//   blockB [64,96): cp*2 -> {W[c0][r2], W[c1][r2]}
__global__ void prep_w_kernel(const float* __restrict__ W) {
    int o = blockIdx.x * 256 + threadIdx.x;
    if (o < 12288) {
        int d    = o / 192;
        int rem  = o - d * 192;
        int h    = rem / 96;
        int rem2 = rem - h * 96;
        int c, r;
        if (rem2 < 64) {
            int cp = rem2 >> 2, t = rem2 & 3;
            c = h * 32 + 2 * cp + (t & 1);
            r = t >> 1;
        } else {
            int rem3 = rem2 - 64;
            int cp = rem3 >> 1;
            c = h * 32 + 2 * cp + (rem3 & 1);
            r = 2;
        }
        g_wsh[o] = W[d * 192 + c * 3 + r];
    }
}

// Shared layout (bytes):
//   wsh  : float[12288]  [0, 49152)     persistent
//   overlay [49152, 67840):  invs rows stride 68 (17408B) / epilogue stage
//            (8 warps x 584 words = 18688B)
//   shs  : float[64*12]  [67840, 70912)
#define SMEM_BYTES 70912

// fill index remap: warp covers 4 edges x 8 consecutive d -> conflict-free STS
__device__ __forceinline__ void fill_map(int idx, int& el, int& d) {
    el = (idx & 3) | ((idx >> 3) & 0x3C);
    d  = ((idx >> 2) & 7) | ((idx >> 6) & 0x38);
}

__device__ __forceinline__ void sh_from_vec(float x, float y, float z, float* o) {
    float r = rsqrtf(x * x + y * y + z * z);
    x *= r; y *= r; z *= r;
    const float s3  = 1.7320508075688772f;
    const float s5  = 2.2360679774997896f;
    const float s15 = 3.8729833462074170f;
    o[0] = 1.0f;
    o[1] = s3 * x;
    o[2] = s3 * y;
    o[3] = s3 * z;
    o[4] = s15 * x * z;
    o[5] = s15 * x * y;
    o[6] = s5 * (y * y - 0.5f * (x * x + z * z));
    o[7] = s15 * y * z;
    o[8] = 0.5f * s15 * (z * z - x * x);
}

__global__ __launch_bounds__(256, 3)
void sh_tensor_embed_kernel(const float* __restrict__ vec,
                            const float* __restrict__ inv,
                            float* __restrict__ out) {
    extern __shared__ char sm[];
    float* smf  = (float*)sm;
    float* invs = (float*)(sm + 49152);
    float* shs  = (float*)(sm + 67840);

    const int tid  = threadIdx.x;
    const int lane = tid & 31;
    const int wid  = tid >> 5;
    const int cp   = lane & 15;          // channel pair within half
    const int eh   = lane >> 4;          // edge octet selector (0..1)
    const int h    = wid & 1;            // channels [32h, 32h+32)
    const int g    = wid >> 1;           // edges [16g, 16g+16)

    // ---- one-time W fill ----
    #pragma unroll
    for (int it = 0; it < 12; it++) {
        int idx = it * 256 + tid;
        ((float4*)smf)[idx] = ((const float4*)g_wsh)[idx];
    }
    // ---- fill first tile's invs + shs ----
    {
        int e0 = blockIdx.x * TILE_E;
        #pragma unroll
        for (int k = 0; k < 16; k++) {
            int el, d;
            fill_map(tid + 256 * k, el, d);
            int e = e0 + el; if (e >= E_EDGES) e = E_EDGES - 1;
            invs[d * 68 + el] = inv[(size_t)e * 64 + d];   // conflict-free STS
        }
        if (tid < TILE_E) {
            int e = e0 + tid; if (e >= E_EDGES) e = E_EDGES - 1;
            sh_from_vec(vec[(size_t)e * 3], vec[(size_t)e * 3 + 1], vec[(size_t)e * 3 + 2],
                        shs + tid * 12);
        }
    }
    __syncthreads();

    const char* wpA = (const char*)(smf + h * 96 + cp * 4);        // LDS.128 / d
    const char* wpB = (const char*)(smf + h * 96 + 64 + cp * 2);   // LDS.64  / d
    float* stagew = invs + wid * 584;    // overlay (invs dead during epilogue)

    for (int tile = blockIdx.x; tile < NBLOCKS; tile += GRID) {
        const int e0 = tile * TILE_E;
        const bool full = (e0 + TILE_E <= E_EDGES);   // uniform: guard-free hot path

        // ---- mainloop: 2 channels (h*32+2cp,+1) x 8 edges ----
        u64 acc[8][3];
        #pragma unroll
        for (int j = 0; j < 8; j++)
            #pragma unroll
            for (int r = 0; r < 3; r++)
                acc[j][r] = 0ull;

        const float* ip = invs + g * 16 + eh * 8;

        #pragma unroll 2
        for (int d = 0; d < 64; d++) {
            ulonglong2 wab = *(const ulonglong2*)(wpA + d * 768);  // {wv0, wv1}
            u64 wv2        = *(const u64*)      (wpB + d * 768);
            float iv[8];
            *(float4*)&iv[0] = *(const float4*)(ip + d * 68);      // broadcast LDS.128
            *(float4*)&iv[4] = *(const float4*)(ip + d * 68 + 4);
            #pragma unroll
            for (int j = 0; j < 8; j++) {
                u64 pv = dup2(iv[j]);
                acc[j][0] = ffma2(pv, wab.x, acc[j][0]);
                acc[j][1] = ffma2(pv, wab.y, acc[j][1]);
                acc[j][2] = ffma2(pv, wv2,   acc[j][2]);
            }
        }
        __syncthreads();                 // invs reads done -> stage overlay safe

        // ---- prefetch next tile while epilogue runs ----
        const int nt = tile + GRID;
        const bool nxt = nt < NBLOCKS;
        float pv[16];
        float vx = 0.f, vy = 0.f, vz = 0.f;
        if (nxt) {
            int ne0 = nt * TILE_E;
            #pragma unroll
            for (int k = 0; k < 16; k++) {
                int el, d;
                fill_map(tid + 256 * k, el, d);
                int e = ne0 + el; if (e >= E_EDGES) e = E_EDGES - 1;
                pv[k] = inv[(size_t)e * 64 + d];
            }
            if (tid < TILE_E) {
                int e = ne0 + tid; if (e >= E_EDGES) e = E_EDGES - 1;
                vx = vec[(size_t)e * 3];
                vy = vec[(size_t)e * 3 + 1];
                vz = vec[(size_t)e * 3 + 2];
            }
        }

        // ---- epilogue: 8 rounds; stage 2 edges/round, coalesced copy-out ----
        #pragma unroll
        for (int s = 0; s < 8; s++) {
            {
                int el = g * 16 + eh * 8 + s;
                const float* sb = shs + el * 12;
                float4 sa  = *(const float4*)sb;
                float4 sbv = *(const float4*)(sb + 4);
                float  s8  = sb[8];
                float sv[9] = {sa.x, sa.y, sa.z, sa.w, sbv.x, sbv.y, sbv.z, sbv.w, s8};
                float wa[3], wb[3];
                #pragma unroll
                for (int r = 0; r < 3; r++) { wa[r] = lo32(acc[s][r]); wb[r] = hi32(acc[s][r]); }
                float v[18];
                #pragma unroll
                for (int k = 0; k < 9; k++) {
                    int r = (k == 0) ? 0 : ((k < 4) ? 1 : 2);
                    v[k]     = sv[k] * wa[r];
                    v[9 + k] = sv[k] * wb[r];
                }
                float* rowp = stagew + eh * 292 + cp * 18;
                #pragma unroll
                for (int p = 0; p < 9; p++)
                    *(float2*)(rowp + 2 * p) = make_float2(v[2 * p], v[2 * p + 1]);
            }
            __syncwarp();
            if (full) {
                #pragma unroll
                for (int t = 0; t < 2; t++) {
                    int e = e0 + g * 16 + t * 8 + s;
                    const float4* src = (const float4*)(stagew + t * 292);
                    float4* dst = (float4*)(out + (size_t)e * 576 + h * 288);
                    dst[lane]      = src[lane];
                    dst[lane + 32] = src[lane + 32];
                    if (lane < 8) dst[lane + 64] = src[lane + 64];
                }
            } else {
                #pragma unroll
                for (int t = 0; t < 2; t++) {
                    int e = e0 + g * 16 + t * 8 + s;
                    if (e < E_EDGES) {
                        const float4* src = (const float4*)(stagew + t * 292);
                        float4* dst = (float4*)(out + (size_t)e * 576 + h * 288);
                        dst[lane]      = src[lane];
                        dst[lane + 32] = src[lane + 32];
                        if (lane < 8) dst[lane + 64] = src[lane + 64];
                    }
                }
            }
            __syncwarp();
        }
        __syncthreads();                 // stage reads done -> invs refill safe

        // ---- commit prefetched tile (conflict-free STS) ----
        if (nxt) {
            #pragma unroll
            for (int k = 0; k < 16; k++) {
                int el, d;
                fill_map(tid + 256 * k, el, d);
                invs[d * 68 + el] = pv[k];
            }
            if (tid < TILE_E)
                sh_from_vec(vx, vy, vz, shs + tid * 12);
        }
        __syncthreads();
    }
}

extern "C" void kernel_launch(void* const* d_in, const int* in_sizes, int n_in,
                              void* d_out, int out_size) {
    const float* vec = nullptr;
    const float* inv = nullptr;
    const float* W   = nullptr;
    for (int i = 0; i < n_in; i++) {
        if      (in_sizes[i] == E_EDGES * 3)  vec = (const float*)d_in[i];
        else if (in_sizes[i] == E_EDGES * 64) inv = (const float*)d_in[i];
        else if (in_sizes[i] == 64 * 192)     W   = (const float*)d_in[i];
    }
    prep_w_kernel<<<48, 256>>>(W);
    cudaFuncSetAttribute(sh_tensor_embed_kernel,
                         cudaFuncAttributeMaxDynamicSharedMemorySize, SMEM_BYTES);
    sh_tensor_embed_kernel<<<GRID, 256, SMEM_BYTES>>>(vec, inv, (float*)d_out);
}